// round 3
// baseline (speedup 1.0000x reference)
#include <cuda_runtime.h>
#include <cstdint>

#define NB   64
#define NPG  1024
#define NFEA 8
#define MIN_DIST 2.9f
#define T2CLAMP 1e-12f

// collapse kernel tiling
#define JCHUNKS 16
#define CHUNK_J (NPG / JCHUNKS)   // 64
#define CTHREADS 256

// accumulators: 0 recon_sum, 1 vol_sum, 2 elec_num, 3 elec_cnt, 4 coll_sum, 5 field_sum
__device__ double g_acc[6];

__global__ void k_zero() {
    if (threadIdx.x < 6) g_acc[threadIdx.x] = 0.0;
}

// ---------------- block reduction helper ----------------
// MODE: 0 = sum, 1 = min, 2 = max.  blockDim.x == 256 (8 warps).
template <int MODE>
__device__ __forceinline__ float blockReduce(float v, float* sbuf) {
    const int lane = threadIdx.x & 31;
    const int wid  = threadIdx.x >> 5;
#pragma unroll
    for (int o = 16; o; o >>= 1) {
        float u = __shfl_down_sync(0xffffffffu, v, o);
        v = (MODE == 0) ? (v + u) : (MODE == 1 ? fminf(v, u) : fmaxf(v, u));
    }
    if (lane == 0) sbuf[wid] = v;
    __syncthreads();
    if (wid == 0) {
        v = (lane < 8) ? sbuf[lane] : (MODE == 0 ? 0.0f : sbuf[0]);
#pragma unroll
        for (int o = 16; o; o >>= 1) {
            float u = __shfl_down_sync(0xffffffffu, v, o);
            v = (MODE == 0) ? (v + u) : (MODE == 1 ? fminf(v, u) : fmaxf(v, u));
        }
        if (lane == 0) sbuf[0] = v;
    }
    __syncthreads();
    float r = sbuf[0];
    __syncthreads();   // protect sbuf reuse by next call
    return r;
}

// ---------------- stats kernel: recon, volume, electrode, field ----------------
// grid = NB blocks, 256 threads, 4 points / thread.
__global__ __launch_bounds__(256) void k_stats(
    const float* __restrict__ pred,
    const float* __restrict__ tru,
    const float* __restrict__ org,
    const float* __restrict__ nfeat)
{
    __shared__ float sbuf[8];
    const int b = blockIdx.x;
    const int t = threadIdx.x;

    float px[4], py[4], pz[4], ox[4], oy[4], oz[4];
    float rsum = 0.0f;

#pragma unroll
    for (int k = 0; k < 4; k++) {
        const int idx = b * NPG + t + k * 256;
        const float* pp = pred + 3 * idx;
        const float* tt = tru  + 3 * idx;
        const float* oo = org  + 3 * idx;
        px[k] = pp[0]; py[k] = pp[1]; pz[k] = pp[2];
        const float dx = px[k] - tt[0];
        const float dy = py[k] - tt[1];
        const float dz = pz[k] - tt[2];
        rsum += dx * dx + dy * dy + dz * dz;
        ox[k] = oo[0]; oy[k] = oo[1]; oz[k] = oo[2];
    }

    // local 4-way min/max
    float pmnx = fminf(fminf(px[0], px[1]), fminf(px[2], px[3]));
    float pmxx = fmaxf(fmaxf(px[0], px[1]), fmaxf(px[2], px[3]));
    float pmny = fminf(fminf(py[0], py[1]), fminf(py[2], py[3]));
    float pmxy = fmaxf(fmaxf(py[0], py[1]), fmaxf(py[2], py[3]));
    float pmnz = fminf(fminf(pz[0], pz[1]), fminf(pz[2], pz[3]));
    float pmxz = fmaxf(fmaxf(pz[0], pz[1]), fmaxf(pz[2], pz[3]));
    float omnx = fminf(fminf(ox[0], ox[1]), fminf(ox[2], ox[3]));
    float omxx = fmaxf(fmaxf(ox[0], ox[1]), fmaxf(ox[2], ox[3]));
    float omny = fminf(fminf(oy[0], oy[1]), fminf(oy[2], oy[3]));
    float omxy = fmaxf(fmaxf(oy[0], oy[1]), fmaxf(oy[2], oy[3]));
    float omnz = fminf(fminf(oz[0], oz[1]), fminf(oz[2], oz[3]));
    float omxz = fmaxf(fmaxf(oz[0], oz[1]), fmaxf(oz[2], oz[3]));
    float szp  = pz[0] + pz[1] + pz[2] + pz[3];

    const float PMNX = blockReduce<1>(pmnx, sbuf);
    const float PMXX = blockReduce<2>(pmxx, sbuf);
    const float PMNY = blockReduce<1>(pmny, sbuf);
    const float PMXY = blockReduce<2>(pmxy, sbuf);
    const float PMNZ = blockReduce<1>(pmnz, sbuf);
    const float PMXZ = blockReduce<2>(pmxz, sbuf);
    const float OMNX = blockReduce<1>(omnx, sbuf);
    const float OMXX = blockReduce<2>(omxx, sbuf);
    const float OMNY = blockReduce<1>(omny, sbuf);
    const float OMXY = blockReduce<2>(omxy, sbuf);
    const float OMNZ = blockReduce<1>(omnz, sbuf);
    const float OMXZ = blockReduce<2>(omxz, sbuf);
    const float SZP  = blockReduce<0>(szp,  sbuf);
    const float RS   = blockReduce<0>(rsum, sbuf);

    // electrode mask from original z extremes (no FMA contraction: match reference arith)
    const float zr   = __fsub_rn(OMXZ, OMNZ);
    const float thlo = __fadd_rn(OMNZ, __fmul_rn(0.15f, zr));
    const float thhi = __fsub_rn(OMXZ, __fmul_rn(0.15f, zr));

    float esum = 0.0f, ecnt = 0.0f;
#pragma unroll
    for (int k = 0; k < 4; k++) {
        const bool m = (oz[k] <= thlo) || (oz[k] >= thhi);
        if (m) {
            const float dx = px[k] - ox[k];
            const float dy = py[k] - oy[k];
            const float dz = pz[k] - oz[k];
            esum += dx * dx + dy * dy + dz * dz;
            ecnt += 1.0f;
        }
    }
    const float ES = blockReduce<0>(esum, sbuf);
    const float EC = blockReduce<0>(ecnt, sbuf);

    if (t == 0) {
        atomicAdd(&g_acc[0], (double)RS);
        atomicAdd(&g_acc[2], (double)ES);
        atomicAdd(&g_acc[3], (double)EC);

        // volume penalty
        const float pdx = PMXX - PMNX, pdy = PMXY - PMNY, pdz = PMXZ - PMNZ;
        const float odx = OMXX - OMNX, ody = OMXY - OMNY, odz = OMXZ - OMNZ;
        const float rx = (pdx - odx) / (odx + 1e-8f);
        const float ry = (pdy - ody) / (ody + 1e-8f);
        const float rz = (pdz - odz) / (odz + 1e-8f);
        const float xy_pen = fmaxf(rx - 0.02f, 0.0f) + fmaxf(ry - 0.02f, 0.0f);
        const float z_pen  = fmaxf(rz, 0.0f);
        atomicAdd(&g_acc[1], (double)(xy_pen + 2.0f * z_pen));

        // field term
        const float zcom  = SZP * (1.0f / 1024.0f);
        const float znorm = (zcom - PMNZ) / ((PMXZ - PMNZ) + 1e-8f);
        const float v = nfeat[(size_t)b * NPG * NFEA + (NFEA - 3)];
        const float target = (v > 0.0f) ? 0.6f : 0.4f;
        const float dvz = znorm - target;
        const float contrib = (fabsf(v) >= 1e-6f) ? dvz * dvz : 0.0f;
        atomicAdd(&g_acc[5], (double)contrib);
    }
}

// ---------------- collapse kernel ----------------
// grid = (JCHUNKS, NB). Each block: all 1024 rows x CHUNK_J columns of one batch.
// 256 threads, 4 rows/thread in registers; j chunk in SMEM as float4(x,y,z,|p|^2).
__global__ __launch_bounds__(CTHREADS) void k_collapse(const float* __restrict__ pred)
{
    __shared__ float4 sj[CHUNK_J];
    __shared__ float sred[8];
    const int b  = blockIdx.y;
    const int jc = blockIdx.x;
    const int t  = threadIdx.x;
    const int jbase = jc * CHUNK_J;

    if (t < CHUNK_J) {
        const int j = jbase + t;
        const float* p = pred + 3 * (size_t)(b * NPG + j);
        const float x = p[0], y = p[1], z = p[2];
        sj[t] = make_float4(x, y, z, fmaf(x, x, fmaf(y, y, z * z)));
    }

    float xi[4], yi[4], zi[4], si[4];
#pragma unroll
    for (int k = 0; k < 4; k++) {
        const int i = t + k * 256;
        const float* p = pred + 3 * (size_t)(b * NPG + i);
        xi[k] = p[0]; yi[k] = p[1]; zi[k] = p[2];
        si[k] = fmaf(xi[k], xi[k], fmaf(yi[k], yi[k], zi[k] * zi[k]));
    }
    __syncthreads();

    float acc = 0.0f;
#pragma unroll 4
    for (int jj = 0; jj < CHUNK_J; jj++) {
        const float4 q = sj[jj];
#pragma unroll
        for (int k = 0; k < 4; k++) {
            const float dot = fmaf(xi[k], q.x, fmaf(yi[k], q.y, zi[k] * q.z));
            float d2 = fmaf(-2.0f, dot, si[k] + q.w);
            d2 = fmaxf(d2, T2CLAMP);
            float d;
            asm("sqrt.approx.f32 %0, %1;" : "=f"(d) : "f"(d2));
            const float v = fmaxf(MIN_DIST - d, 0.0f);
            acc = fmaf(v, v, acc);
        }
    }

    // Subtract the self-pair (i == j) if this block's j-window contains row i.
    // Row i = t + 256k lies in [jbase, jbase+CHUNK_J) for at most one k; the
    // identical arithmetic guarantees exact cancellation with the main loop.
#pragma unroll
    for (int k = 0; k < 4; k++) {
        const int i  = t + k * 256;
        const int jj = i - jbase;
        if (jj >= 0 && jj < CHUNK_J) {
            const float4 q = sj[jj];
            const float dot = fmaf(xi[k], q.x, fmaf(yi[k], q.y, zi[k] * q.z));
            float d2 = fmaf(-2.0f, dot, si[k] + q.w);
            d2 = fmaxf(d2, T2CLAMP);
            float d;
            asm("sqrt.approx.f32 %0, %1;" : "=f"(d) : "f"(d2));
            const float v = fmaxf(MIN_DIST - d, 0.0f);
            acc = fmaf(-v, v, acc);
        }
    }

    const float S = blockReduce<0>(acc, sred);
    if (t == 0) atomicAdd(&g_acc[4], (double)S);
}

// ---------------- finalize ----------------
__global__ void k_finalize(float* __restrict__ out, int out_size)
{
    if (threadIdx.x == 0) {
        const double recon  = g_acc[0] / (double)(NB * NPG * 3);
        const double volume = g_acc[1] / (double)NB;
        const double elec   = g_acc[2] / (g_acc[3] * 3.0);
        const double coll   = g_acc[4] / ((double)NB * (double)NPG * (double)(NPG - 1));
        const double field  = g_acc[5] / (double)NB;
        const double total  = 1.0 * recon + 10.0 * volume + 50.0 * elec
                            + 5.0 * coll + 2.0 * field;
        double vals[6] = { total, recon, volume, elec, coll, field };
        for (int i = 0; i < 6 && i < out_size; i++) out[i] = (float)vals[i];
    }
}

extern "C" void kernel_launch(void* const* d_in, const int* in_sizes, int n_in,
                              void* d_out, int out_size)
{
    // Resolve inputs by element count (robust to metadata ordering):
    //   coords  : 3 arrays of 196608 f32 (pred, true, original — relative order kept)
    //   nfeat   : 524288 f32
    //   batchvec: 65536 i64 (unused)
    int coord_idx[3]; int n_coord = 0;
    int nf_idx = -1, bv_idx = -1;
    for (int i = 0; i < n_in; i++) {
        if (in_sizes[i] == NB * NPG * 3) { if (n_coord < 3) coord_idx[n_coord] = i; n_coord++; }
        else if (in_sizes[i] == NB * NPG * NFEA) nf_idx = i;
        else if (in_sizes[i] == NB * NPG) bv_idx = i;
    }

    const float *pred, *tru, *org, *nf;
    if (n_coord == 3 && nf_idx >= 0) {
        if (bv_idx >= 0 && bv_idx < coord_idx[0]) {
            // alphabetical metadata ordering: batch_vector, node_features, original, pred, true
            org  = (const float*)d_in[coord_idx[0]];
            pred = (const float*)d_in[coord_idx[1]];
            tru  = (const float*)d_in[coord_idx[2]];
        } else {
            // insertion ordering: pred, true, original, node_features, batch_vector
            pred = (const float*)d_in[coord_idx[0]];
            tru  = (const float*)d_in[coord_idx[1]];
            org  = (const float*)d_in[coord_idx[2]];
        }
        nf = (const float*)d_in[nf_idx];
    } else {
        // fallback: setup_inputs insertion order
        pred = (const float*)d_in[0];
        tru  = (const float*)d_in[1];
        org  = (const float*)d_in[2];
        nf   = (const float*)d_in[3];
    }

    float* out = (float*)d_out;

    k_zero<<<1, 32>>>();
    k_stats<<<NB, 256>>>(pred, tru, org, nf);
    k_collapse<<<dim3(JCHUNKS, NB), CTHREADS>>>(pred);
    k_finalize<<<1, 32>>>(out, out_size);
}